// round 6
// baseline (speedup 1.0000x reference)
#include <cuda_runtime.h>
#include <math.h>
#include <stdint.h>

#define NN 512
#define EMB 64
#define HID 128
#define G4 512   // 4*HID
#define IN2 128  // 2*EMB

// ---- scratch (device globals; no allocations allowed) ----
__device__ float g_input_feat[NN * IN2];   // [node][128]
__device__ float g_ihc[NN * G4];           // x@W_ih^T + b_ih + b_hh per node
__device__ int   g_orders[NN * NN];        // [start][step]
__device__ float g_WhhT[HID * G4];         // W_hh transposed [d][j]
__device__ float g_embed[NN * HID];        // mean LSTM output per sequence
__device__ float g_logits[4 * NN];

// ---------------- Threefry2x32 (JAX-compatible) ----------------
__device__ __forceinline__ uint32_t rotl32(uint32_t x, int d) {
    return (x << d) | (x >> (32 - d));
}

__device__ __forceinline__ void threefry(uint32_t k0, uint32_t k1,
                                         uint32_t& x0, uint32_t& x1) {
    uint32_t ks2 = k0 ^ k1 ^ 0x1BD11BDAu;
    x0 += k0; x1 += k1;
    x0 += x1; x1 = rotl32(x1, 13); x1 ^= x0;
    x0 += x1; x1 = rotl32(x1, 15); x1 ^= x0;
    x0 += x1; x1 = rotl32(x1, 26); x1 ^= x0;
    x0 += x1; x1 = rotl32(x1, 6);  x1 ^= x0;
    x0 += k1; x1 += ks2 + 1u;
    x0 += x1; x1 = rotl32(x1, 17); x1 ^= x0;
    x0 += x1; x1 = rotl32(x1, 29); x1 ^= x0;
    x0 += x1; x1 = rotl32(x1, 16); x1 ^= x0;
    x0 += x1; x1 = rotl32(x1, 24); x1 ^= x0;
    x0 += ks2; x1 += k0 + 2u;
    x0 += x1; x1 = rotl32(x1, 13); x1 ^= x0;
    x0 += x1; x1 = rotl32(x1, 15); x1 ^= x0;
    x0 += x1; x1 = rotl32(x1, 26); x1 ^= x0;
    x0 += x1; x1 = rotl32(x1, 6);  x1 ^= x0;
    x0 += k0; x1 += k1 + 3u;
    x0 += x1; x1 = rotl32(x1, 17); x1 ^= x0;
    x0 += x1; x1 = rotl32(x1, 29); x1 ^= x0;
    x0 += x1; x1 = rotl32(x1, 16); x1 ^= x0;
    x0 += x1; x1 = rotl32(x1, 24); x1 ^= x0;
    x0 += k1; x1 += ks2 + 4u;
    x0 += x1; x1 = rotl32(x1, 13); x1 ^= x0;
    x0 += x1; x1 = rotl32(x1, 15); x1 ^= x0;
    x0 += x1; x1 = rotl32(x1, 26); x1 ^= x0;
    x0 += x1; x1 = rotl32(x1, 6);  x1 ^= x0;
    x0 += ks2; x1 += k0 + 5u;
}

__device__ __forceinline__ float sigf(float x) {
    return 1.0f / (1.0f + expf(-x));
}

// ---------------- Kernel A: node_feat / neigh_feat ----------------
__global__ void k_embed(const int* __restrict__ tags,
                        const float* __restrict__ adj,
                        const float* __restrict__ W_emb,
                        const float* __restrict__ b_emb) {
    int i = blockIdx.x;
    int d = threadIdx.x;  // 64
    __shared__ int stags[NN];
    for (int j = d; j < NN; j += 64) stags[j] = tags[j];
    __syncthreads();
    float nf = W_emb[stags[i] * EMB + d] + b_emb[d];
    float acc = 0.f;
    const float* arow = adj + (size_t)i * NN;
    for (int j = 0; j < NN; j++) {
        if (arow[j] > 0.5f) acc += W_emb[stags[j] * EMB + d];
    }
    g_input_feat[i * IN2 + d] = nf;
    g_input_feat[i * IN2 + EMB + d] = acc + b_emb[d];
}

// ---------------- Kernel B: transpose W_hh ----------------
__global__ void k_prep_whh(const float* __restrict__ W_hh) {
    int idx = blockIdx.x * blockDim.x + threadIdx.x;  // 512*128
    if (idx < G4 * HID) {
        int j = idx / HID, d = idx % HID;
        g_WhhT[d * G4 + j] = W_hh[idx];
    }
}

// ---------------- Kernel C: per-node input-gate contribution ----------------
__global__ void k_ihc(const float* __restrict__ W_ih,
                      const float* __restrict__ b_ih,
                      const float* __restrict__ b_hh) {
    int node = blockIdx.x;
    int j = threadIdx.x;  // 512
    __shared__ float sx[IN2];
    if (j < IN2) sx[j] = g_input_feat[node * IN2 + j];
    __syncthreads();
    const float* wr = W_ih + j * IN2;
    float acc = 0.f;
#pragma unroll 8
    for (int d = 0; d < IN2; d++) acc += sx[d] * wr[d];
    g_ihc[node * G4 + j] = acc + b_ih[j] + b_hh[j];
}

// ---------------- Kernel D: greedy noisy random-walk orderings ----------------
// JAX threefry (partitionable): subkey_s = tf(key42,(0,s)); key_t = tf(subkey,(0,t));
// bits[i] = hi^lo of tf(key_t,(0,i)); uniform per JAX _uniform; argmax of
// (adj[cur,i]+noise[i]) over unvisited (monotone equiv of exp/norm/mask path).
__global__ void k_orders(const float* __restrict__ adj) {
    int s = blockIdx.x;
    int tid = threadIdx.x;  // 256
    __shared__ unsigned char smask[NN];
    __shared__ int scur;
    __shared__ float rv[256];
    __shared__ int ri[256];
    smask[tid] = 1; smask[tid + 256] = 1;
    __syncthreads();
    if (tid == 0) { smask[s] = 0; scur = s; g_orders[s * NN] = s; }
    __syncthreads();

    uint32_t k1 = 0u, k2 = (uint32_t)s;
    threefry(0u, 42u, k1, k2);  // split(key(42), 512)[s]

    const float scale = 0.1f - 0.01f;
    for (int t = 0; t < NN - 1; t++) {
        uint32_t f1 = 0u, f2 = (uint32_t)t;
        threefry(k1, k2, f1, f2);  // fold_in
        int cur = scur;
        const float* arow = adj + (size_t)cur * NN;
        float bv = -INFINITY; int bi = -1;
#pragma unroll
        for (int c = 0; c < 2; c++) {
            int i = tid + c * 256;
            uint32_t a = 0u, b = (uint32_t)i;
            threefry(f1, f2, a, b);
            uint32_t bits = a ^ b;
            float u = __uint_as_float((bits >> 9) | 0x3f800000u) - 1.0f;
            float noise = fmaxf(0.01f, __fadd_rn(__fmul_rn(u, scale), 0.01f));
            float val = arow[i] + noise;
            if (smask[i] && val > bv) { bv = val; bi = i; }  // lower idx wins ties
        }
        rv[tid] = bv; ri[tid] = bi;
        __syncthreads();
        for (int off = 128; off > 0; off >>= 1) {
            if (tid < off) {
                float ov = rv[tid + off]; int oi = ri[tid + off];
                if (ov > rv[tid] || (ov == rv[tid] && oi < ri[tid])) {
                    rv[tid] = ov; ri[tid] = oi;
                }
            }
            __syncthreads();
        }
        if (tid == 0) {
            int nxt = ri[0];
            g_orders[s * NN + t + 1] = nxt;
            smask[nxt] = 0; scur = nxt;
        }
        __syncthreads();
    }
}

// ---------------- Kernel E: LSTM (4 sequences per block) ----------------
#define NB 4
__global__ void __launch_bounds__(256) k_lstm() {
    int bb = blockIdx.x;     // 0..127
    int tid = threadIdx.x;   // 0..255
    __shared__ float sh[NB][HID];
    __shared__ float sc[NB][HID];
    __shared__ float sg[NB][G4];
    __shared__ int snode[NB];

    for (int i = tid; i < NB * HID; i += 256) {
        (&sh[0][0])[i] = 0.f; (&sc[0][0])[i] = 0.f;
    }
    int p0 = tid, p1 = tid + 256;
    int b0 = p0 >> 7, d0 = p0 & 127;
    int b1 = p1 >> 7, d1 = p1 & 127;
    float e0 = 0.f, e1 = 0.f;
    int base = bb * NB;
    int j0 = tid * 2;
    __syncthreads();

    for (int t = 0; t < NN; t++) {
        if (tid < NB) snode[tid] = g_orders[(base + tid) * NN + t];
        __syncthreads();

        // gates[b][j0..j0+1] = ihc[node_b] + h_b @ W_hh^T
        float acc[NB][2];
#pragma unroll
        for (int b = 0; b < NB; b++) {
            float2 v = *(const float2*)&g_ihc[snode[b] * G4 + j0];
            acc[b][0] = v.x; acc[b][1] = v.y;
        }
#pragma unroll 4
        for (int d = 0; d < HID; d++) {
            float2 w = *(const float2*)&g_WhhT[d * G4 + j0];
#pragma unroll
            for (int b = 0; b < NB; b++) {
                float hv = sh[b][d];
                acc[b][0] = fmaf(hv, w.x, acc[b][0]);
                acc[b][1] = fmaf(hv, w.y, acc[b][1]);
            }
        }
#pragma unroll
        for (int b = 0; b < NB; b++) {
            sg[b][j0] = acc[b][0]; sg[b][j0 + 1] = acc[b][1];
        }
        __syncthreads();

        // activations: each thread owns 2 (b,d) cells
        {
            float gi = sg[b0][d0], gf = sg[b0][128 + d0];
            float gg = sg[b0][256 + d0], go = sg[b0][384 + d0];
            float cc = sigf(gf) * sc[b0][d0] + sigf(gi) * tanhf(gg);
            sc[b0][d0] = cc;
            float hh = sigf(go) * tanhf(cc);
            sh[b0][d0] = hh; e0 += hh;
        }
        {
            float gi = sg[b1][d1], gf = sg[b1][128 + d1];
            float gg = sg[b1][256 + d1], go = sg[b1][384 + d1];
            float cc = sigf(gf) * sc[b1][d1] + sigf(gi) * tanhf(gg);
            sc[b1][d1] = cc;
            float hh = sigf(go) * tanhf(cc);
            sh[b1][d1] = hh; e1 += hh;
        }
        __syncthreads();
    }
    g_embed[(base + b0) * HID + d0] = e0 * (1.0f / 512.0f);
    g_embed[(base + b1) * HID + d1] = e1 * (1.0f / 512.0f);
}

// ---------------- Kernel F: 4-head MLP -> logits ----------------
__global__ void k_mlp(const float* __restrict__ W1s,
                      const float* __restrict__ b1s,
                      const float* __restrict__ W2s,
                      const float* __restrict__ b2s) {
    int n = blockIdx.x;
    int h = threadIdx.x;  // 128
    __shared__ float se[HID];
    __shared__ float red[128];
    se[h] = g_embed[n * HID + h];
    __syncthreads();
    for (int k = 0; k < 4; k++) {
        const float* W1 = W1s + k * HID * HID;
        float acc = b1s[k * HID + h];
#pragma unroll 8
        for (int d = 0; d < HID; d++) acc += se[d] * W1[d * HID + h];
        float r = fmaxf(acc, 0.f) * W2s[k * HID + h];
        red[h] = r;
        __syncthreads();
        for (int off = 64; off > 0; off >>= 1) {
            if (h < off) red[h] += red[h + off];
            __syncthreads();
        }
        if (h == 0) g_logits[k * NN + n] = red[0] + b2s[k];
        __syncthreads();
    }
}

// ---------------- Kernel G: loss + ensemble output ----------------
__global__ void k_final(const int* __restrict__ label,
                        const float* __restrict__ var_raw,
                        float* __restrict__ out) {
    int n = threadIdx.x;  // 512
    __shared__ float cw[4];
    __shared__ float red[NN];
    if (n < 4) {
        float x = var_raw[n];
        // softplus, stable
        cw[n] = (x > 0.f) ? (x + log1pf(expf(-x))) : log1pf(expf(x));
    }
    __syncthreads();
    if (n == 0) {
        float s = cw[0] + cw[1] + cw[2] + cw[3];
        cw[0] /= s; cw[1] /= s; cw[2] /= s; cw[3] /= s;
    }
    __syncthreads();
    float lab = (float)label[0];
    float y = 0.f, lsum = 0.f;
#pragma unroll
    for (int k = 0; k < 4; k++) {
        float L = g_logits[k * NN + n];
        // log_sigmoid(L) and log_sigmoid(-L), stable
        float ls_pos = (L > 0.f) ? -log1pf(expf(-L)) : (L - log1pf(expf(L)));
        float ls_neg = (L < 0.f) ? -log1pf(expf(L)) : (-L - log1pf(expf(-L)));
        lsum += -(lab * ls_pos + (1.f - lab) * ls_neg);
        y += cw[k] * sigf(L);
    }
    red[n] = lsum;
    __syncthreads();
    for (int off = 256; off > 0; off >>= 1) {
        if (n < off) red[n] += red[n + off];
        __syncthreads();
    }
    if (n == 0) out[0] = red[0] * (1.0f / 512.0f);  // sum_k mean_n
    out[1 + n] = y;
}

// ---------------- launcher ----------------
extern "C" void kernel_launch(void* const* d_in, const int* in_sizes, int n_in,
                              void* d_out, int out_size) {
    const int*   tags    = (const int*)d_in[0];
    const float* adj     = (const float*)d_in[1];
    const int*   label   = (const int*)d_in[2];
    const float* W_emb   = (const float*)d_in[3];
    const float* b_emb   = (const float*)d_in[4];
    const float* W_ih    = (const float*)d_in[5];
    const float* W_hh    = (const float*)d_in[6];
    const float* b_ih    = (const float*)d_in[7];
    const float* b_hh    = (const float*)d_in[8];
    const float* W1s     = (const float*)d_in[9];
    const float* b1s     = (const float*)d_in[10];
    const float* W2s     = (const float*)d_in[11];
    const float* b2s     = (const float*)d_in[12];
    const float* var_raw = (const float*)d_in[13];
    float* out = (float*)d_out;

    k_embed<<<NN, 64>>>(tags, adj, W_emb, b_emb);
    k_prep_whh<<<(G4 * HID + 255) / 256, 256>>>(W_hh);
    k_ihc<<<NN, G4>>>(W_ih, b_ih, b_hh);
    k_orders<<<NN, 256>>>(adj);
    k_lstm<<<NN / NB, 256>>>();
    k_mlp<<<NN, 128>>>(W1s, b1s, W2s, b2s);
    k_final<<<1, NN>>>(label, var_raw, out);
    (void)in_sizes; (void)n_in; (void)out_size;
}

// round 7
// speedup vs baseline: 1.8020x; 1.8020x over previous
#include <cuda_runtime.h>
#include <math.h>
#include <stdint.h>

#define NN 512
#define EMB 64
#define HID 128
#define G4 512   // 4*HID
#define IN2 128  // 2*EMB

#define SMEM_D 104          // W rows resident in SMEM
#define RREM (HID - SMEM_D) // 24 W rows resident in registers
// dynamic smem floats: sW + sh2(dup pairs) + sg
#define LSTM_SMEM_FLOATS (SMEM_D * G4 + HID * 8 + 4 * G4)
#define LSTM_SMEM_BYTES (LSTM_SMEM_FLOATS * 4)

// ---- scratch (device globals; no allocations allowed) ----
__device__ float g_input_feat[NN * IN2];   // [node][128]
__device__ float g_ihc[NN * G4];           // x@W_ih^T + b_ih + b_hh per node
__device__ int   g_orders[NN * NN];        // [start][step]
__device__ float g_WhhT[HID * G4];         // W_hh transposed [d][j]
__device__ float g_embed[NN * HID];        // mean LSTM output per sequence
__device__ float g_logits[4 * NN];

// packed fp32x2 FMA (Blackwell): acc = a*b + acc, lanewise IEEE fp32
#define FFMA2(acc, a, b) \
    asm("fma.rn.f32x2 %0, %1, %2, %0;" : "+l"(acc) : "l"(a), "l"(b))

// ---------------- Threefry2x32 (JAX-compatible) ----------------
__device__ __forceinline__ uint32_t rotl32(uint32_t x, int d) {
    return (x << d) | (x >> (32 - d));
}

__device__ __forceinline__ void threefry(uint32_t k0, uint32_t k1,
                                         uint32_t& x0, uint32_t& x1) {
    uint32_t ks2 = k0 ^ k1 ^ 0x1BD11BDAu;
    x0 += k0; x1 += k1;
    x0 += x1; x1 = rotl32(x1, 13); x1 ^= x0;
    x0 += x1; x1 = rotl32(x1, 15); x1 ^= x0;
    x0 += x1; x1 = rotl32(x1, 26); x1 ^= x0;
    x0 += x1; x1 = rotl32(x1, 6);  x1 ^= x0;
    x0 += k1; x1 += ks2 + 1u;
    x0 += x1; x1 = rotl32(x1, 17); x1 ^= x0;
    x0 += x1; x1 = rotl32(x1, 29); x1 ^= x0;
    x0 += x1; x1 = rotl32(x1, 16); x1 ^= x0;
    x0 += x1; x1 = rotl32(x1, 24); x1 ^= x0;
    x0 += ks2; x1 += k0 + 2u;
    x0 += x1; x1 = rotl32(x1, 13); x1 ^= x0;
    x0 += x1; x1 = rotl32(x1, 15); x1 ^= x0;
    x0 += x1; x1 = rotl32(x1, 26); x1 ^= x0;
    x0 += x1; x1 = rotl32(x1, 6);  x1 ^= x0;
    x0 += k0; x1 += k1 + 3u;
    x0 += x1; x1 = rotl32(x1, 17); x1 ^= x0;
    x0 += x1; x1 = rotl32(x1, 29); x1 ^= x0;
    x0 += x1; x1 = rotl32(x1, 16); x1 ^= x0;
    x0 += x1; x1 = rotl32(x1, 24); x1 ^= x0;
    x0 += k1; x1 += ks2 + 4u;
    x0 += x1; x1 = rotl32(x1, 13); x1 ^= x0;
    x0 += x1; x1 = rotl32(x1, 15); x1 ^= x0;
    x0 += x1; x1 = rotl32(x1, 26); x1 ^= x0;
    x0 += x1; x1 = rotl32(x1, 6);  x1 ^= x0;
    x0 += ks2; x1 += k0 + 5u;
}

__device__ __forceinline__ float sigf(float x) {
    return 1.0f / (1.0f + expf(-x));
}

// ---------------- Kernel A: node_feat / neigh_feat ----------------
__global__ void k_embed(const int* __restrict__ tags,
                        const float* __restrict__ adj,
                        const float* __restrict__ W_emb,
                        const float* __restrict__ b_emb) {
    int i = blockIdx.x;
    int d = threadIdx.x;  // 64
    __shared__ int stags[NN];
    for (int j = d; j < NN; j += 64) stags[j] = tags[j];
    __syncthreads();
    float nf = W_emb[stags[i] * EMB + d] + b_emb[d];
    float acc = 0.f;
    const float* arow = adj + (size_t)i * NN;
    for (int j = 0; j < NN; j++) {
        if (arow[j] > 0.5f) acc += W_emb[stags[j] * EMB + d];
    }
    g_input_feat[i * IN2 + d] = nf;
    g_input_feat[i * IN2 + EMB + d] = acc + b_emb[d];
}

// ---------------- Kernel B: transpose W_hh ----------------
__global__ void k_prep_whh(const float* __restrict__ W_hh) {
    int idx = blockIdx.x * blockDim.x + threadIdx.x;  // 512*128
    if (idx < G4 * HID) {
        int j = idx / HID, d = idx % HID;
        g_WhhT[d * G4 + j] = W_hh[idx];
    }
}

// ---------------- Kernel C: per-node input-gate contribution ----------------
__global__ void k_ihc(const float* __restrict__ W_ih,
                      const float* __restrict__ b_ih,
                      const float* __restrict__ b_hh) {
    int node = blockIdx.x;
    int j = threadIdx.x;  // 512
    __shared__ float sx[IN2];
    if (j < IN2) sx[j] = g_input_feat[node * IN2 + j];
    __syncthreads();
    const float* wr = W_ih + j * IN2;
    float acc = 0.f;
#pragma unroll 8
    for (int d = 0; d < IN2; d++) acc += sx[d] * wr[d];
    g_ihc[node * G4 + j] = acc + b_ih[j] + b_hh[j];
}

// ---------------- Kernel D: greedy noisy random-walk orderings ----------------
// Same PRNG math as the passing R5 kernel (partitionable threefry), but the
// argmax is a packed-u64 shuffle reduction (val bits || (511-i); max => same
// value order, ties resolve to lowest index), and the next step's noise
// (independent of cur) is computed before the reduction to hide latency.
__device__ __forceinline__ void walk_noise(uint32_t k1, uint32_t k2, int t,
                                           int tid, float* n0, float* n1) {
    const float scale = 0.1f - 0.01f;
    uint32_t f1 = 0u, f2 = (uint32_t)t;
    threefry(k1, k2, f1, f2);  // fold_in
    uint32_t a0 = 0u, b0 = (uint32_t)tid;
    threefry(f1, f2, a0, b0);
    uint32_t bits0 = a0 ^ b0;
    float u0 = __uint_as_float((bits0 >> 9) | 0x3f800000u) - 1.0f;
    *n0 = fmaxf(0.01f, __fadd_rn(__fmul_rn(u0, scale), 0.01f));
    uint32_t a1 = 0u, b1 = (uint32_t)(tid + 256);
    threefry(f1, f2, a1, b1);
    uint32_t bits1 = a1 ^ b1;
    float u1 = __uint_as_float((bits1 >> 9) | 0x3f800000u) - 1.0f;
    *n1 = fmaxf(0.01f, __fadd_rn(__fmul_rn(u1, scale), 0.01f));
}

__global__ void __launch_bounds__(256) k_orders(const float* __restrict__ adj) {
    int s = blockIdx.x;
    int tid = threadIdx.x;  // 256
    int lane = tid & 31, warp = tid >> 5;
    __shared__ unsigned char smask[NN];
    __shared__ unsigned long long wred[8];
    __shared__ int scur;
    smask[tid] = 1; smask[tid + 256] = 1;
    __syncthreads();
    if (tid == 0) { smask[s] = 0; scur = s; g_orders[s * NN] = s; }

    uint32_t k1 = 0u, k2 = (uint32_t)s;
    threefry(0u, 42u, k1, k2);  // split(key(42), 512)[s]

    float n0, n1;
    walk_noise(k1, k2, 0, tid, &n0, &n1);
    __syncthreads();

    for (int t = 0; t < NN - 1; t++) {
        int cur = scur;
        const float* arow = adj + (size_t)cur * NN;
        float v0 = arow[tid] + n0;
        float v1 = arow[tid + 256] + n1;
        unsigned long long key0 = smask[tid]
            ? ((((unsigned long long)__float_as_uint(v0)) << 32) |
               (unsigned long long)(unsigned)(NN - 1 - tid)) : 0ull;
        unsigned long long key1 = smask[tid + 256]
            ? ((((unsigned long long)__float_as_uint(v1)) << 32) |
               (unsigned long long)(unsigned)(NN - 1 - (tid + 256))) : 0ull;
        unsigned long long key = key1 > key0 ? key1 : key0;

        // precompute next step's noise (independent of cur) to overlap
        if (t + 1 < NN - 1) walk_noise(k1, k2, t + 1, tid, &n0, &n1);

#pragma unroll
        for (int off = 16; off > 0; off >>= 1) {
            unsigned long long o = __shfl_xor_sync(0xffffffffu, key, off);
            if (o > key) key = o;
        }
        if (lane == 0) wred[warp] = key;
        __syncthreads();
        if (tid == 0) {
            unsigned long long best = wred[0];
#pragma unroll
            for (int w = 1; w < 8; w++) if (wred[w] > best) best = wred[w];
            int nxt = (NN - 1) - (int)(unsigned)(best & 0xffffffffu);
            g_orders[s * NN + t + 1] = nxt;
            smask[nxt] = 0;
            scur = nxt;
        }
        __syncthreads();
    }
}

// ---------------- Kernel E: LSTM (4 sequences per block, FFMA2) ----------------
// W_hh^T rows [0,SMEM_D) live in SMEM, rows [SMEM_D,128) live in registers.
// h stored as duplicated fp32 pairs (h,h) so the inner loop is pure
// LDS.64(w) + 2x LDS.128(h-pairs) + 4x fma.rn.f32x2 per d.
__global__ void __launch_bounds__(256) k_lstm() {
    extern __shared__ float smem[];
    float* sW  = smem;                      // [SMEM_D][512]
    float* sh2 = smem + SMEM_D * G4;        // [128][4 pairs] = 1024 floats
    float* sg  = sh2 + HID * 8;             // [4][512]

    int bb = blockIdx.x;     // 0..127
    int tid = threadIdx.x;   // 0..255
    int base = bb * 4;
    int j0 = tid * 2;

    // stage SMEM W
    {
        const float4* src = (const float4*)g_WhhT;
        float4* dst = (float4*)sW;
        for (int i = tid; i < SMEM_D * G4 / 4; i += 256) dst[i] = src[i];
    }
    // register-resident W tail
    unsigned long long wreg[RREM];
#pragma unroll
    for (int r = 0; r < RREM; r++)
        wreg[r] = *(const unsigned long long*)&g_WhhT[(SMEM_D + r) * G4 + j0];

    for (int i = tid; i < HID * 8; i += 256) sh2[i] = 0.f;

    int dA = tid & 127, bA = tid >> 7, bB = bA + 2;
    float cA = 0.f, cB = 0.f, eA = 0.f, eB = 0.f;

    // prefetch t=0 input contributions
    unsigned long long acc[4];
    {
        int nd[4];
#pragma unroll
        for (int b = 0; b < 4; b++) nd[b] = g_orders[(base + b) * NN];
#pragma unroll
        for (int b = 0; b < 4; b++)
            acc[b] = *(const unsigned long long*)&g_ihc[nd[b] * G4 + j0];
    }
    __syncthreads();

    for (int t = 0; t < NN; t++) {
        // ---- recurrent GEMM: gates[b][j0,j0+1] += h[b] @ WhhT ----
#pragma unroll 8
        for (int d = 0; d < SMEM_D; d++) {
            unsigned long long w = *(const unsigned long long*)&sW[d * G4 + j0];
            ulonglong2 h01 = *(const ulonglong2*)&sh2[d * 8];
            ulonglong2 h23 = *(const ulonglong2*)&sh2[d * 8 + 4];
            FFMA2(acc[0], h01.x, w);
            FFMA2(acc[1], h01.y, w);
            FFMA2(acc[2], h23.x, w);
            FFMA2(acc[3], h23.y, w);
        }
#pragma unroll
        for (int r = 0; r < RREM; r++) {
            int d = SMEM_D + r;
            ulonglong2 h01 = *(const ulonglong2*)&sh2[d * 8];
            ulonglong2 h23 = *(const ulonglong2*)&sh2[d * 8 + 4];
            FFMA2(acc[0], h01.x, wreg[r]);
            FFMA2(acc[1], h01.y, wreg[r]);
            FFMA2(acc[2], h23.x, wreg[r]);
            FFMA2(acc[3], h23.y, wreg[r]);
        }
#pragma unroll
        for (int b = 0; b < 4; b++)
            *(unsigned long long*)&sg[b * G4 + j0] = acc[b];
        __syncthreads();

        // prefetch next step's ihc while activations run
        if (t + 1 < NN) {
            int nd[4];
#pragma unroll
            for (int b = 0; b < 4; b++) nd[b] = g_orders[(base + b) * NN + t + 1];
#pragma unroll
            for (int b = 0; b < 4; b++)
                acc[b] = *(const unsigned long long*)&g_ihc[nd[b] * G4 + j0];
        }

        // ---- activations: this thread owns (bA,dA) and (bB,dA) ----
        {
            const float* sgb = sg + bA * G4;
            float gi = sgb[dA], gf = sgb[128 + dA];
            float gg = sgb[256 + dA], go = sgb[384 + dA];
            cA = sigf(gf) * cA + sigf(gi) * tanhf(gg);
            float h = sigf(go) * tanhf(cA);
            eA += h;
            *(float2*)&sh2[dA * 8 + bA * 2] = make_float2(h, h);
        }
        {
            const float* sgb = sg + bB * G4;
            float gi = sgb[dA], gf = sgb[128 + dA];
            float gg = sgb[256 + dA], go = sgb[384 + dA];
            cB = sigf(gf) * cB + sigf(gi) * tanhf(gg);
            float h = sigf(go) * tanhf(cB);
            eB += h;
            *(float2*)&sh2[dA * 8 + bB * 2] = make_float2(h, h);
        }
        __syncthreads();
    }
    g_embed[(base + bA) * HID + dA] = eA * (1.0f / 512.0f);
    g_embed[(base + bB) * HID + dA] = eB * (1.0f / 512.0f);
}

// ---------------- Kernel F: 4-head MLP -> logits ----------------
__global__ void k_mlp(const float* __restrict__ W1s,
                      const float* __restrict__ b1s,
                      const float* __restrict__ W2s,
                      const float* __restrict__ b2s) {
    int n = blockIdx.x;
    int h = threadIdx.x;  // 128
    __shared__ float se[HID];
    __shared__ float red[128];
    se[h] = g_embed[n * HID + h];
    __syncthreads();
    for (int k = 0; k < 4; k++) {
        const float* W1 = W1s + k * HID * HID;
        float acc = b1s[k * HID + h];
#pragma unroll 8
        for (int d = 0; d < HID; d++) acc += se[d] * W1[d * HID + h];
        float r = fmaxf(acc, 0.f) * W2s[k * HID + h];
        red[h] = r;
        __syncthreads();
        for (int off = 64; off > 0; off >>= 1) {
            if (h < off) red[h] += red[h + off];
            __syncthreads();
        }
        if (h == 0) g_logits[k * NN + n] = red[0] + b2s[k];
        __syncthreads();
    }
}

// ---------------- Kernel G: loss + ensemble output ----------------
__global__ void k_final(const int* __restrict__ label,
                        const float* __restrict__ var_raw,
                        float* __restrict__ out) {
    int n = threadIdx.x;  // 512
    __shared__ float cw[4];
    __shared__ float red[NN];
    if (n < 4) {
        float x = var_raw[n];
        cw[n] = (x > 0.f) ? (x + log1pf(expf(-x))) : log1pf(expf(x));
    }
    __syncthreads();
    if (n == 0) {
        float s = cw[0] + cw[1] + cw[2] + cw[3];
        cw[0] /= s; cw[1] /= s; cw[2] /= s; cw[3] /= s;
    }
    __syncthreads();
    float lab = (float)label[0];
    float y = 0.f, lsum = 0.f;
#pragma unroll
    for (int k = 0; k < 4; k++) {
        float L = g_logits[k * NN + n];
        float ls_pos = (L > 0.f) ? -log1pf(expf(-L)) : (L - log1pf(expf(L)));
        float ls_neg = (L < 0.f) ? -log1pf(expf(L)) : (-L - log1pf(expf(-L)));
        lsum += -(lab * ls_pos + (1.f - lab) * ls_neg);
        y += cw[k] * sigf(L);
    }
    red[n] = lsum;
    __syncthreads();
    for (int off = 256; off > 0; off >>= 1) {
        if (n < off) red[n] += red[n + off];
        __syncthreads();
    }
    if (n == 0) out[0] = red[0] * (1.0f / 512.0f);  // sum_k mean_n
    out[1 + n] = y;
}

// ---------------- launcher ----------------
extern "C" void kernel_launch(void* const* d_in, const int* in_sizes, int n_in,
                              void* d_out, int out_size) {
    const int*   tags    = (const int*)d_in[0];
    const float* adj     = (const float*)d_in[1];
    const int*   label   = (const int*)d_in[2];
    const float* W_emb   = (const float*)d_in[3];
    const float* b_emb   = (const float*)d_in[4];
    const float* W_ih    = (const float*)d_in[5];
    const float* W_hh    = (const float*)d_in[6];
    const float* b_ih    = (const float*)d_in[7];
    const float* b_hh    = (const float*)d_in[8];
    const float* W1s     = (const float*)d_in[9];
    const float* b1s     = (const float*)d_in[10];
    const float* W2s     = (const float*)d_in[11];
    const float* b2s     = (const float*)d_in[12];
    const float* var_raw = (const float*)d_in[13];
    float* out = (float*)d_out;

    cudaFuncSetAttribute(k_lstm, cudaFuncAttributeMaxDynamicSharedMemorySize,
                         LSTM_SMEM_BYTES);

    k_embed<<<NN, 64>>>(tags, adj, W_emb, b_emb);
    k_prep_whh<<<(G4 * HID + 255) / 256, 256>>>(W_hh);
    k_ihc<<<NN, G4>>>(W_ih, b_ih, b_hh);
    k_orders<<<NN, 256>>>(adj);
    k_lstm<<<NN / 4, 256, LSTM_SMEM_BYTES>>>();
    k_mlp<<<NN, 128>>>(W1s, b1s, W2s, b2s);
    k_final<<<1, NN>>>(label, var_raw, out);
    (void)in_sizes; (void)n_in; (void)out_size;
}

// round 8
// speedup vs baseline: 2.1824x; 1.2111x over previous
#include <cuda_runtime.h>
#include <math.h>
#include <stdint.h>

#define NN 512
#define EMB 64
#define HID 128
#define G4 512   // 4*HID
#define IN2 128  // 2*EMB

#define SMEM_D 48           // W rows resident in SMEM
#define RREM (HID - SMEM_D) // 80 W rows resident in registers (160 regs)
// dynamic smem floats: sW + sh2(dup pairs) + sg
#define LSTM_SMEM_FLOATS (SMEM_D * G4 + HID * 8 + 4 * G4)
#define LSTM_SMEM_BYTES (LSTM_SMEM_FLOATS * 4)

// ---- scratch (device globals; no allocations allowed) ----
__device__ float g_input_feat[NN * IN2];   // [node][128]
__device__ float g_ihc[NN * G4];           // x@W_ih^T + b_ih + b_hh per node
__device__ int   g_orders[NN * NN];        // [start][step]
__device__ float g_WhhT[HID * G4];         // W_hh transposed [d][j]
__device__ float g_embed[NN * HID];        // mean LSTM output per sequence
__device__ float g_logits[4 * NN];

// packed fp32x2 FMA (Blackwell): acc = a*b + acc, lanewise IEEE fp32
#define FFMA2(acc, a, b) \
    asm("fma.rn.f32x2 %0, %1, %2, %0;" : "+l"(acc) : "l"(a), "l"(b))

// ---------------- Threefry2x32 (JAX-compatible) ----------------
__device__ __forceinline__ uint32_t rotl32(uint32_t x, int d) {
    return (x << d) | (x >> (32 - d));
}

__device__ __forceinline__ void threefry(uint32_t k0, uint32_t k1,
                                         uint32_t& x0, uint32_t& x1) {
    uint32_t ks2 = k0 ^ k1 ^ 0x1BD11BDAu;
    x0 += k0; x1 += k1;
    x0 += x1; x1 = rotl32(x1, 13); x1 ^= x0;
    x0 += x1; x1 = rotl32(x1, 15); x1 ^= x0;
    x0 += x1; x1 = rotl32(x1, 26); x1 ^= x0;
    x0 += x1; x1 = rotl32(x1, 6);  x1 ^= x0;
    x0 += k1; x1 += ks2 + 1u;
    x0 += x1; x1 = rotl32(x1, 17); x1 ^= x0;
    x0 += x1; x1 = rotl32(x1, 29); x1 ^= x0;
    x0 += x1; x1 = rotl32(x1, 16); x1 ^= x0;
    x0 += x1; x1 = rotl32(x1, 24); x1 ^= x0;
    x0 += ks2; x1 += k0 + 2u;
    x0 += x1; x1 = rotl32(x1, 13); x1 ^= x0;
    x0 += x1; x1 = rotl32(x1, 15); x1 ^= x0;
    x0 += x1; x1 = rotl32(x1, 26); x1 ^= x0;
    x0 += x1; x1 = rotl32(x1, 6);  x1 ^= x0;
    x0 += k0; x1 += k1 + 3u;
    x0 += x1; x1 = rotl32(x1, 17); x1 ^= x0;
    x0 += x1; x1 = rotl32(x1, 29); x1 ^= x0;
    x0 += x1; x1 = rotl32(x1, 16); x1 ^= x0;
    x0 += x1; x1 = rotl32(x1, 24); x1 ^= x0;
    x0 += k1; x1 += ks2 + 4u;
    x0 += x1; x1 = rotl32(x1, 13); x1 ^= x0;
    x0 += x1; x1 = rotl32(x1, 15); x1 ^= x0;
    x0 += x1; x1 = rotl32(x1, 26); x1 ^= x0;
    x0 += x1; x1 = rotl32(x1, 6);  x1 ^= x0;
    x0 += ks2; x1 += k0 + 5u;
}

// fast activations (err ~1e-6; recurrence is contractive)
__device__ __forceinline__ float fsig(float x) {
    return __fdividef(1.0f, 1.0f + __expf(-x));
}
__device__ __forceinline__ float ftanh(float x) {
    return __fdividef(2.0f, 1.0f + __expf(-2.0f * x)) - 1.0f;
}
__device__ __forceinline__ float sigf(float x) {  // accurate (non-LSTM paths)
    return 1.0f / (1.0f + expf(-x));
}

// ---------------- Kernel A: node_feat / neigh_feat ----------------
__global__ void k_embed(const int* __restrict__ tags,
                        const float* __restrict__ adj,
                        const float* __restrict__ W_emb,
                        const float* __restrict__ b_emb) {
    int i = blockIdx.x;
    int d = threadIdx.x;  // 64
    __shared__ int stags[NN];
    for (int j = d; j < NN; j += 64) stags[j] = tags[j];
    __syncthreads();
    float nf = W_emb[stags[i] * EMB + d] + b_emb[d];
    float acc = 0.f;
    const float* arow = adj + (size_t)i * NN;
    for (int j = 0; j < NN; j++) {
        if (arow[j] > 0.5f) acc += W_emb[stags[j] * EMB + d];
    }
    g_input_feat[i * IN2 + d] = nf;
    g_input_feat[i * IN2 + EMB + d] = acc + b_emb[d];
}

// ---------------- Kernel B: transpose W_hh ----------------
__global__ void k_prep_whh(const float* __restrict__ W_hh) {
    int idx = blockIdx.x * blockDim.x + threadIdx.x;  // 512*128
    if (idx < G4 * HID) {
        int j = idx / HID, d = idx % HID;
        g_WhhT[d * G4 + j] = W_hh[idx];
    }
}

// ---------------- Kernel C: per-node input-gate contribution ----------------
__global__ void k_ihc(const float* __restrict__ W_ih,
                      const float* __restrict__ b_ih,
                      const float* __restrict__ b_hh) {
    int node = blockIdx.x;
    int j = threadIdx.x;  // 512
    __shared__ float sx[IN2];
    if (j < IN2) sx[j] = g_input_feat[node * IN2 + j];
    __syncthreads();
    const float* wr = W_ih + j * IN2;
    float acc = 0.f;
#pragma unroll 8
    for (int d = 0; d < IN2; d++) acc += sx[d] * wr[d];
    g_ihc[node * G4 + j] = acc + b_ih[j] + b_hh[j];
}

// ---------------- Kernel D: greedy noisy random-walk orderings ----------------
// Partitionable threefry (verified bit-exact R5/R6). fold_in ciphers for all
// steps are precomputed ONCE into smem (they were ~30% of per-step issue).
__device__ __forceinline__ float walk_noise1(uint32_t f1, uint32_t f2, int i) {
    const float scale = 0.1f - 0.01f;
    uint32_t a = 0u, b = (uint32_t)i;
    threefry(f1, f2, a, b);
    uint32_t bits = a ^ b;
    float u = __uint_as_float((bits >> 9) | 0x3f800000u) - 1.0f;
    return fmaxf(0.01f, __fadd_rn(__fmul_rn(u, scale), 0.01f));
}

__global__ void __launch_bounds__(256) k_orders(const float* __restrict__ adj) {
    int s = blockIdx.x;
    int tid = threadIdx.x;  // 256
    int lane = tid & 31, warp = tid >> 5;
    __shared__ uint32_t fi1[NN], fi2[NN];
    __shared__ unsigned char smask[NN];
    __shared__ unsigned long long wred[8];
    __shared__ int scur;

    uint32_t k1 = 0u, k2 = (uint32_t)s;
    threefry(0u, 42u, k1, k2);  // split(key(42), 512)[s]

    // fold_in table: fi[t] = threefry(subkey, (0,t)) for all steps
#pragma unroll
    for (int c = 0; c < 2; c++) {
        int t = tid + c * 256;
        uint32_t f1 = 0u, f2 = (uint32_t)t;
        threefry(k1, k2, f1, f2);
        fi1[t] = f1; fi2[t] = f2;
    }
    smask[tid] = 1; smask[tid + 256] = 1;
    __syncthreads();
    if (tid == 0) { smask[s] = 0; scur = s; g_orders[s * NN] = s; }

    float n0 = walk_noise1(fi1[0], fi2[0], tid);
    float n1 = walk_noise1(fi1[0], fi2[0], tid + 256);
    __syncthreads();

    for (int t = 0; t < NN - 1; t++) {
        int cur = scur;
        const float* arow = adj + (size_t)cur * NN;
        float v0 = arow[tid] + n0;
        float v1 = arow[tid + 256] + n1;
        unsigned long long key0 = smask[tid]
            ? ((((unsigned long long)__float_as_uint(v0)) << 32) |
               (unsigned long long)(unsigned)(NN - 1 - tid)) : 0ull;
        unsigned long long key1 = smask[tid + 256]
            ? ((((unsigned long long)__float_as_uint(v1)) << 32) |
               (unsigned long long)(unsigned)(NN - 1 - (tid + 256))) : 0ull;
        unsigned long long key = key1 > key0 ? key1 : key0;

        // overlap next step's noise (cur-independent) with the reduction
        if (t + 1 < NN - 1) {
            uint32_t f1 = fi1[t + 1], f2 = fi2[t + 1];
            n0 = walk_noise1(f1, f2, tid);
            n1 = walk_noise1(f1, f2, tid + 256);
        }

#pragma unroll
        for (int off = 16; off > 0; off >>= 1) {
            unsigned long long o = __shfl_xor_sync(0xffffffffu, key, off);
            if (o > key) key = o;
        }
        if (lane == 0) wred[warp] = key;
        __syncthreads();
        if (tid == 0) {
            unsigned long long best = wred[0];
#pragma unroll
            for (int w = 1; w < 8; w++) if (wred[w] > best) best = wred[w];
            int nxt = (NN - 1) - (int)(unsigned)(best & 0xffffffffu);
            g_orders[s * NN + t + 1] = nxt;
            smask[nxt] = 0;
            scur = nxt;
        }
        __syncthreads();
    }
}

// ---------------- Kernel E: LSTM (4 sequences per block, FFMA2) ----------------
// W_hh^T rows [0,SMEM_D) in SMEM, rows [SMEM_D,128) in registers (160 regs).
// h stored as duplicated fp32 pairs so the hot loop is LDS + fma.rn.f32x2 only.
__global__ void __launch_bounds__(256) k_lstm() {
    extern __shared__ float smem[];
    float* sW  = smem;                      // [SMEM_D][512]
    float* sh2 = smem + SMEM_D * G4;        // [128][4 dup pairs] = 1024 floats
    float* sg  = sh2 + HID * 8;             // [4][512]

    int bb = blockIdx.x;     // 0..127
    int tid = threadIdx.x;   // 0..255
    int base = bb * 4;
    int j0 = tid * 2;

    // stage SMEM W rows
    {
        const float4* src = (const float4*)g_WhhT;
        float4* dst = (float4*)sW;
        for (int i = tid; i < SMEM_D * G4 / 4; i += 256) dst[i] = src[i];
    }
    // register-resident W tail (this thread's j-pair for rows SMEM_D..127)
    unsigned long long wreg[RREM];
#pragma unroll
    for (int r = 0; r < RREM; r++)
        wreg[r] = *(const unsigned long long*)&g_WhhT[(SMEM_D + r) * G4 + j0];

    for (int i = tid; i < HID * 8; i += 256) sh2[i] = 0.f;

    int dA = tid & 127, bA = tid >> 7, bB = bA + 2;
    float cA = 0.f, cB = 0.f, eA = 0.f, eB = 0.f;

    // prefetch t=0 input contributions
    unsigned long long acc[4];
    {
        int nd[4];
#pragma unroll
        for (int b = 0; b < 4; b++) nd[b] = g_orders[(base + b) * NN];
#pragma unroll
        for (int b = 0; b < 4; b++)
            acc[b] = *(const unsigned long long*)&g_ihc[nd[b] * G4 + j0];
    }
    __syncthreads();

    for (int t = 0; t < NN; t++) {
        // ---- recurrent GEMM: gates[b][j0,j0+1] += h[b] @ WhhT ----
#pragma unroll 8
        for (int d = 0; d < SMEM_D; d++) {
            unsigned long long w = *(const unsigned long long*)&sW[d * G4 + j0];
            ulonglong2 h01 = *(const ulonglong2*)&sh2[d * 8];
            ulonglong2 h23 = *(const ulonglong2*)&sh2[d * 8 + 4];
            FFMA2(acc[0], h01.x, w);
            FFMA2(acc[1], h01.y, w);
            FFMA2(acc[2], h23.x, w);
            FFMA2(acc[3], h23.y, w);
        }
#pragma unroll
        for (int r = 0; r < RREM; r++) {
            int d = SMEM_D + r;
            ulonglong2 h01 = *(const ulonglong2*)&sh2[d * 8];
            ulonglong2 h23 = *(const ulonglong2*)&sh2[d * 8 + 4];
            FFMA2(acc[0], h01.x, wreg[r]);
            FFMA2(acc[1], h01.y, wreg[r]);
            FFMA2(acc[2], h23.x, wreg[r]);
            FFMA2(acc[3], h23.y, wreg[r]);
        }
#pragma unroll
        for (int b = 0; b < 4; b++)
            *(unsigned long long*)&sg[b * G4 + j0] = acc[b];
        __syncthreads();

        // prefetch next step's ihc while activations run
        if (t + 1 < NN) {
            int nd[4];
#pragma unroll
            for (int b = 0; b < 4; b++) nd[b] = g_orders[(base + b) * NN + t + 1];
#pragma unroll
            for (int b = 0; b < 4; b++)
                acc[b] = *(const unsigned long long*)&g_ihc[nd[b] * G4 + j0];
        }

        // ---- activations: this thread owns (bA,dA) and (bB,dA) ----
        {
            const float* sgb = sg + bA * G4;
            float gi = sgb[dA], gf = sgb[128 + dA];
            float gg = sgb[256 + dA], go = sgb[384 + dA];
            cA = fsig(gf) * cA + fsig(gi) * ftanh(gg);
            float h = fsig(go) * ftanh(cA);
            eA += h;
            *(float2*)&sh2[dA * 8 + bA * 2] = make_float2(h, h);
        }
        {
            const float* sgb = sg + bB * G4;
            float gi = sgb[dA], gf = sgb[128 + dA];
            float gg = sgb[256 + dA], go = sgb[384 + dA];
            cB = fsig(gf) * cB + fsig(gi) * ftanh(gg);
            float h = fsig(go) * ftanh(cB);
            eB += h;
            *(float2*)&sh2[dA * 8 + bB * 2] = make_float2(h, h);
        }
        __syncthreads();
    }
    g_embed[(base + bA) * HID + dA] = eA * (1.0f / 512.0f);
    g_embed[(base + bB) * HID + dA] = eB * (1.0f / 512.0f);
}

// ---------------- Kernel F: 4-head MLP -> logits ----------------
__global__ void k_mlp(const float* __restrict__ W1s,
                      const float* __restrict__ b1s,
                      const float* __restrict__ W2s,
                      const float* __restrict__ b2s) {
    int n = blockIdx.x;
    int h = threadIdx.x;  // 128
    __shared__ float se[HID];
    __shared__ float red[128];
    se[h] = g_embed[n * HID + h];
    __syncthreads();
    for (int k = 0; k < 4; k++) {
        const float* W1 = W1s + k * HID * HID;
        float acc = b1s[k * HID + h];
#pragma unroll 8
        for (int d = 0; d < HID; d++) acc += se[d] * W1[d * HID + h];
        float r = fmaxf(acc, 0.f) * W2s[k * HID + h];
        red[h] = r;
        __syncthreads();
        for (int off = 64; off > 0; off >>= 1) {
            if (h < off) red[h] += red[h + off];
            __syncthreads();
        }
        if (h == 0) g_logits[k * NN + n] = red[0] + b2s[k];
        __syncthreads();
    }
}

// ---------------- Kernel G: loss + ensemble output ----------------
__global__ void k_final(const int* __restrict__ label,
                        const float* __restrict__ var_raw,
                        float* __restrict__ out) {
    int n = threadIdx.x;  // 512
    __shared__ float cw[4];
    __shared__ float red[NN];
    if (n < 4) {
        float x = var_raw[n];
        cw[n] = (x > 0.f) ? (x + log1pf(expf(-x))) : log1pf(expf(x));
    }
    __syncthreads();
    if (n == 0) {
        float s = cw[0] + cw[1] + cw[2] + cw[3];
        cw[0] /= s; cw[1] /= s; cw[2] /= s; cw[3] /= s;
    }
    __syncthreads();
    float lab = (float)label[0];
    float y = 0.f, lsum = 0.f;
#pragma unroll
    for (int k = 0; k < 4; k++) {
        float L = g_logits[k * NN + n];
        float ls_pos = (L > 0.f) ? -log1pf(expf(-L)) : (L - log1pf(expf(L)));
        float ls_neg = (L < 0.f) ? -log1pf(expf(L)) : (-L - log1pf(expf(-L)));
        lsum += -(lab * ls_pos + (1.f - lab) * ls_neg);
        y += cw[k] * sigf(L);
    }
    red[n] = lsum;
    __syncthreads();
    for (int off = 256; off > 0; off >>= 1) {
        if (n < off) red[n] += red[n + off];
        __syncthreads();
    }
    if (n == 0) out[0] = red[0] * (1.0f / 512.0f);  // sum_k mean_n
    out[1 + n] = y;
}

// ---------------- launcher ----------------
extern "C" void kernel_launch(void* const* d_in, const int* in_sizes, int n_in,
                              void* d_out, int out_size) {
    const int*   tags    = (const int*)d_in[0];
    const float* adj     = (const float*)d_in[1];
    const int*   label   = (const int*)d_in[2];
    const float* W_emb   = (const float*)d_in[3];
    const float* b_emb   = (const float*)d_in[4];
    const float* W_ih    = (const float*)d_in[5];
    const float* W_hh    = (const float*)d_in[6];
    const float* b_ih    = (const float*)d_in[7];
    const float* b_hh    = (const float*)d_in[8];
    const float* W1s     = (const float*)d_in[9];
    const float* b1s     = (const float*)d_in[10];
    const float* W2s     = (const float*)d_in[11];
    const float* b2s     = (const float*)d_in[12];
    const float* var_raw = (const float*)d_in[13];
    float* out = (float*)d_out;

    cudaFuncSetAttribute(k_lstm, cudaFuncAttributeMaxDynamicSharedMemorySize,
                         LSTM_SMEM_BYTES);

    k_embed<<<NN, 64>>>(tags, adj, W_emb, b_emb);
    k_prep_whh<<<(G4 * HID + 255) / 256, 256>>>(W_hh);
    k_ihc<<<NN, G4>>>(W_ih, b_ih, b_hh);
    k_orders<<<NN, 256>>>(adj);
    k_lstm<<<NN / 4, 256, LSTM_SMEM_BYTES>>>();
    k_mlp<<<NN, 128>>>(W1s, b1s, W2s, b2s);
    k_final<<<1, NN>>>(label, var_raw, out);
    (void)in_sizes; (void)n_in; (void)out_size;
}

// round 9
// speedup vs baseline: 2.3044x; 1.0559x over previous
#include <cuda_runtime.h>
#include <math.h>
#include <stdint.h>

#define NN 512
#define EMB 64
#define HID 128
#define G4 512   // 4*HID
#define IN2 128  // 2*EMB

#define SMEM_D 40           // W rows resident in SMEM
#define RREM (HID - SMEM_D) // 88 W rows resident in registers (176 regs)
// dynamic smem floats: sW + sh2(dup pairs) + sg
#define LSTM_SMEM_FLOATS (SMEM_D * G4 + HID * 8 + 4 * G4)
#define LSTM_SMEM_BYTES (LSTM_SMEM_FLOATS * 4)

// ---- scratch (device globals; no allocations allowed) ----
__device__ float g_input_feat[NN * IN2];   // [node][128]
__device__ float g_ihc[NN * G4];           // x@W_ih^T + b_ih + b_hh per node
__device__ int   g_orders[NN * NN];        // [start][step]
__device__ float g_WhhT[HID * G4];         // W_hh transposed [d][j]
__device__ float g_embed[NN * HID];        // mean LSTM output per sequence
__device__ float g_logits[4 * NN];

// packed fp32x2 FMA (Blackwell): acc = a*b + acc, lanewise IEEE fp32
#define FFMA2(acc, a, b) \
    asm("fma.rn.f32x2 %0, %1, %2, %0;" : "+l"(acc) : "l"(a), "l"(b))

// ---------------- Threefry2x32 (JAX-compatible) ----------------
__device__ __forceinline__ uint32_t rotl32(uint32_t x, int d) {
    return (x << d) | (x >> (32 - d));
}

__device__ __forceinline__ void threefry(uint32_t k0, uint32_t k1,
                                         uint32_t& x0, uint32_t& x1) {
    uint32_t ks2 = k0 ^ k1 ^ 0x1BD11BDAu;
    x0 += k0; x1 += k1;
    x0 += x1; x1 = rotl32(x1, 13); x1 ^= x0;
    x0 += x1; x1 = rotl32(x1, 15); x1 ^= x0;
    x0 += x1; x1 = rotl32(x1, 26); x1 ^= x0;
    x0 += x1; x1 = rotl32(x1, 6);  x1 ^= x0;
    x0 += k1; x1 += ks2 + 1u;
    x0 += x1; x1 = rotl32(x1, 17); x1 ^= x0;
    x0 += x1; x1 = rotl32(x1, 29); x1 ^= x0;
    x0 += x1; x1 = rotl32(x1, 16); x1 ^= x0;
    x0 += x1; x1 = rotl32(x1, 24); x1 ^= x0;
    x0 += ks2; x1 += k0 + 2u;
    x0 += x1; x1 = rotl32(x1, 13); x1 ^= x0;
    x0 += x1; x1 = rotl32(x1, 15); x1 ^= x0;
    x0 += x1; x1 = rotl32(x1, 26); x1 ^= x0;
    x0 += x1; x1 = rotl32(x1, 6);  x1 ^= x0;
    x0 += k0; x1 += k1 + 3u;
    x0 += x1; x1 = rotl32(x1, 17); x1 ^= x0;
    x0 += x1; x1 = rotl32(x1, 29); x1 ^= x0;
    x0 += x1; x1 = rotl32(x1, 16); x1 ^= x0;
    x0 += x1; x1 = rotl32(x1, 24); x1 ^= x0;
    x0 += k1; x1 += ks2 + 4u;
    x0 += x1; x1 = rotl32(x1, 13); x1 ^= x0;
    x0 += x1; x1 = rotl32(x1, 15); x1 ^= x0;
    x0 += x1; x1 = rotl32(x1, 26); x1 ^= x0;
    x0 += x1; x1 = rotl32(x1, 6);  x1 ^= x0;
    x0 += ks2; x1 += k0 + 5u;
}

// fast activations (err ~1e-6; recurrence is contractive)
__device__ __forceinline__ float fsig(float x) {
    return __fdividef(1.0f, 1.0f + __expf(-x));
}
__device__ __forceinline__ float ftanh(float x) {
    return __fdividef(2.0f, 1.0f + __expf(-2.0f * x)) - 1.0f;
}
__device__ __forceinline__ float sigf(float x) {  // accurate (non-LSTM paths)
    return 1.0f / (1.0f + expf(-x));
}

// ---------------- Kernel A: node_feat / neigh_feat ----------------
__global__ void k_embed(const int* __restrict__ tags,
                        const float* __restrict__ adj,
                        const float* __restrict__ W_emb,
                        const float* __restrict__ b_emb) {
    int i = blockIdx.x;
    int d = threadIdx.x;  // 64
    __shared__ int stags[NN];
    for (int j = d; j < NN; j += 64) stags[j] = tags[j];
    __syncthreads();
    float nf = W_emb[stags[i] * EMB + d] + b_emb[d];
    float acc = 0.f;
    const float* arow = adj + (size_t)i * NN;
    for (int j = 0; j < NN; j++) {
        if (arow[j] > 0.5f) acc += W_emb[stags[j] * EMB + d];
    }
    g_input_feat[i * IN2 + d] = nf;
    g_input_feat[i * IN2 + EMB + d] = acc + b_emb[d];
}

// ---------------- Kernel B: transpose W_hh ----------------
__global__ void k_prep_whh(const float* __restrict__ W_hh) {
    int idx = blockIdx.x * blockDim.x + threadIdx.x;  // 512*128
    if (idx < G4 * HID) {
        int j = idx / HID, d = idx % HID;
        g_WhhT[d * G4 + j] = W_hh[idx];
    }
}

// ---------------- Kernel C: per-node input-gate contribution ----------------
__global__ void k_ihc(const float* __restrict__ W_ih,
                      const float* __restrict__ b_ih,
                      const float* __restrict__ b_hh) {
    int node = blockIdx.x;
    int j = threadIdx.x;  // 512
    __shared__ float sx[IN2];
    if (j < IN2) sx[j] = g_input_feat[node * IN2 + j];
    __syncthreads();
    const float* wr = W_ih + j * IN2;
    float acc = 0.f;
#pragma unroll 8
    for (int d = 0; d < IN2; d++) acc += sx[d] * wr[d];
    g_ihc[node * G4 + j] = acc + b_ih[j] + b_hh[j];
}

// ---------------- Kernel D: greedy noisy random-walk orderings ----------------
// Partitionable threefry (bit-exact, verified R5-R7). NEW: candidate filter.
// noise in [0.01, 0.1), so only unvisited i with adj[cur,i] >= maxadj - 0.09001
// can win the argmax (gap >= 1e-5 >> fp32 rounding => selection and ties are
// EXACTLY preserved). Candidates (~9% of unvisited) are ballot-compacted into a
// list; only ceil(nc/32) warps run the threefry cipher.
__device__ __forceinline__ float walk_noise1(uint32_t f1, uint32_t f2, int i) {
    const float scale = 0.1f - 0.01f;
    uint32_t a = 0u, b = (uint32_t)i;
    threefry(f1, f2, a, b);
    uint32_t bits = a ^ b;
    float u = __uint_as_float((bits >> 9) | 0x3f800000u) - 1.0f;
    return fmaxf(0.01f, __fadd_rn(__fmul_rn(u, scale), 0.01f));
}

__global__ void __launch_bounds__(256) k_orders(const float* __restrict__ adj) {
    int s = blockIdx.x;
    int tid = threadIdx.x;  // 256
    int lane = tid & 31, warp = tid >> 5;
    __shared__ uint32_t fi1[NN], fi2[NN];
    __shared__ unsigned char smask[NN];
    __shared__ float wmax[8];
    __shared__ unsigned long long wred[8];
    __shared__ short slist[NN];
    __shared__ int scnt;
    __shared__ int scur;

    uint32_t k1 = 0u, k2 = (uint32_t)s;
    threefry(0u, 42u, k1, k2);  // split(key(42), 512)[s]
#pragma unroll
    for (int c = 0; c < 2; c++) {
        int t = tid + c * 256;
        uint32_t f1 = 0u, f2 = (uint32_t)t;
        threefry(k1, k2, f1, f2);
        fi1[t] = f1; fi2[t] = f2;
    }
    smask[tid] = 1; smask[tid + 256] = 1;
    if (tid == 0) scnt = 0;
    __syncthreads();
    if (tid == 0) { smask[s] = 0; scur = s; g_orders[s * NN] = s; }
    __syncthreads();

    for (int t = 0; t < NN - 1; t++) {
        int cur = scur;
        const float* arow = adj + (size_t)cur * NN;
        float a0 = arow[tid], a1 = arow[tid + 256];
        bool m0 = smask[tid] != 0, m1 = smask[tid + 256] != 0;

        // phase A: masked max of adj row (no ciphers)
        float mx = fmaxf(m0 ? a0 : -1e30f, m1 ? a1 : -1e30f);
#pragma unroll
        for (int off = 16; off > 0; off >>= 1)
            mx = fmaxf(mx, __shfl_xor_sync(0xffffffffu, mx, off));
        if (lane == 0) wmax[warp] = mx;
        __syncthreads();
        float thr = wmax[0];
#pragma unroll
        for (int w = 1; w < 8; w++) thr = fmaxf(thr, wmax[w]);
        float thr2 = thr - 0.09001f;

        // phase B: ballot-compact candidate indices
        bool c0 = m0 && (a0 >= thr2);
        bool c1 = m1 && (a1 >= thr2);
        unsigned bal0 = __ballot_sync(0xffffffffu, c0);
        unsigned bal1 = __ballot_sync(0xffffffffu, c1);
        int cnt = __popc(bal0) + __popc(bal1);
        int basee = 0;
        if (lane == 0 && cnt) basee = atomicAdd(&scnt, cnt);
        basee = __shfl_sync(0xffffffffu, basee, 0);
        unsigned lmask = (1u << lane) - 1u;
        if (c0) slist[basee + __popc(bal0 & lmask)] = (short)tid;
        if (c1) slist[basee + __popc(bal0) + __popc(bal1 & lmask)] =
            (short)(tid + 256);
        __syncthreads();
        int nc = scnt;

        // phase C: ciphers only for candidates
        uint32_t f1 = fi1[t], f2 = fi2[t];
        unsigned long long key = 0ull;
        if (tid < nc) {
            int i = slist[tid];
            float v = arow[i] + walk_noise1(f1, f2, i);
            key = (((unsigned long long)__float_as_uint(v)) << 32) |
                  (unsigned long long)(unsigned)(NN - 1 - i);
        }
        if (tid + 256 < nc) {  // safety for huge candidate sets
            int i = slist[tid + 256];
            float v = arow[i] + walk_noise1(f1, f2, i);
            unsigned long long kk =
                (((unsigned long long)__float_as_uint(v)) << 32) |
                (unsigned long long)(unsigned)(NN - 1 - i);
            if (kk > key) key = kk;
        }
#pragma unroll
        for (int off = 16; off > 0; off >>= 1) {
            unsigned long long o = __shfl_xor_sync(0xffffffffu, key, off);
            if (o > key) key = o;
        }
        if (lane == 0) wred[warp] = key;
        __syncthreads();
        if (tid == 0) {
            unsigned long long best = wred[0];
#pragma unroll
            for (int w = 1; w < 8; w++) if (wred[w] > best) best = wred[w];
            int nxt = (NN - 1) - (int)(unsigned)(best & 0xffffffffu);
            g_orders[s * NN + t + 1] = nxt;
            smask[nxt] = 0;
            scur = nxt;
            scnt = 0;
        }
        __syncthreads();
    }
}

// ---------------- Kernel E: LSTM (4 sequences per block, FFMA2) ----------------
// W_hh^T rows [0,SMEM_D) in SMEM, rows [SMEM_D,128) in registers.
// h stored as duplicated fp32 pairs so the hot loop is LDS + fma.rn.f32x2 only.
// Global prefetch pipelined 2 steps ahead so dependent LDGs hide under the GEMM.
__global__ void __launch_bounds__(256) k_lstm() {
    extern __shared__ float smem[];
    float* sW  = smem;                      // [SMEM_D][512]
    float* sh2 = smem + SMEM_D * G4;        // [128][4 dup pairs] = 1024 floats
    float* sg  = sh2 + HID * 8;             // [4][512]

    int bb = blockIdx.x;     // 0..127
    int tid = threadIdx.x;   // 0..255
    int base = bb * 4;
    int j0 = tid * 2;

    // stage SMEM W rows
    {
        const float4* src = (const float4*)g_WhhT;
        float4* dst = (float4*)sW;
        for (int i = tid; i < SMEM_D * G4 / 4; i += 256) dst[i] = src[i];
    }
    // register-resident W tail (this thread's j-pair for rows SMEM_D..127)
    unsigned long long wreg[RREM];
#pragma unroll
    for (int r = 0; r < RREM; r++)
        wreg[r] = *(const unsigned long long*)&g_WhhT[(SMEM_D + r) * G4 + j0];

    for (int i = tid; i < HID * 8; i += 256) sh2[i] = 0.f;

    int dA = tid & 127, bA = tid >> 7, bB = bA + 2;
    float cA = 0.f, cB = 0.f, eA = 0.f, eB = 0.f;

    // software pipeline: acc holds ihc for step t; tmp prefetches t+1;
    // ndB holds node ids for t+1 (loaded one step earlier).
    unsigned long long acc[4], tmp[4];
    int ndB[4];
    {
        int nd0[4];
#pragma unroll
        for (int b = 0; b < 4; b++) nd0[b] = g_orders[(base + b) * NN];
#pragma unroll
        for (int b = 0; b < 4; b++)
            acc[b] = *(const unsigned long long*)&g_ihc[nd0[b] * G4 + j0];
#pragma unroll
        for (int b = 0; b < 4; b++) ndB[b] = g_orders[(base + b) * NN + 1];
    }
    __syncthreads();

    for (int t = 0; t < NN; t++) {
        // issue next-step prefetches FIRST: they complete under the GEMM
        if (t + 1 < NN) {
#pragma unroll
            for (int b = 0; b < 4; b++)
                tmp[b] = *(const unsigned long long*)&g_ihc[ndB[b] * G4 + j0];
        }
        if (t + 2 < NN) {
#pragma unroll
            for (int b = 0; b < 4; b++)
                ndB[b] = g_orders[(base + b) * NN + t + 2];
        }

        // ---- recurrent GEMM: gates[b][j0,j0+1] += h[b] @ WhhT ----
#pragma unroll 8
        for (int d = 0; d < SMEM_D; d++) {
            unsigned long long w = *(const unsigned long long*)&sW[d * G4 + j0];
            ulonglong2 h01 = *(const ulonglong2*)&sh2[d * 8];
            ulonglong2 h23 = *(const ulonglong2*)&sh2[d * 8 + 4];
            FFMA2(acc[0], h01.x, w);
            FFMA2(acc[1], h01.y, w);
            FFMA2(acc[2], h23.x, w);
            FFMA2(acc[3], h23.y, w);
        }
#pragma unroll
        for (int r = 0; r < RREM; r++) {
            int d = SMEM_D + r;
            ulonglong2 h01 = *(const ulonglong2*)&sh2[d * 8];
            ulonglong2 h23 = *(const ulonglong2*)&sh2[d * 8 + 4];
            FFMA2(acc[0], h01.x, wreg[r]);
            FFMA2(acc[1], h01.y, wreg[r]);
            FFMA2(acc[2], h23.x, wreg[r]);
            FFMA2(acc[3], h23.y, wreg[r]);
        }
#pragma unroll
        for (int b = 0; b < 4; b++)
            *(unsigned long long*)&sg[b * G4 + j0] = acc[b];
        __syncthreads();

        // ---- activations: this thread owns (bA,dA) and (bB,dA) ----
        {
            const float* sgb = sg + bA * G4;
            float gi = sgb[dA], gf = sgb[128 + dA];
            float gg = sgb[256 + dA], go = sgb[384 + dA];
            cA = fsig(gf) * cA + fsig(gi) * ftanh(gg);
            float h = fsig(go) * ftanh(cA);
            eA += h;
            *(float2*)&sh2[dA * 8 + bA * 2] = make_float2(h, h);
        }
        {
            const float* sgb = sg + bB * G4;
            float gi = sgb[dA], gf = sgb[128 + dA];
            float gg = sgb[256 + dA], go = sgb[384 + dA];
            cB = fsig(gf) * cB + fsig(gi) * ftanh(gg);
            float h = fsig(go) * ftanh(cB);
            eB += h;
            *(float2*)&sh2[dA * 8 + bB * 2] = make_float2(h, h);
        }
        // rotate pipeline
#pragma unroll
        for (int b = 0; b < 4; b++) acc[b] = tmp[b];
        __syncthreads();
    }
    g_embed[(base + bA) * HID + dA] = eA * (1.0f / 512.0f);
    g_embed[(base + bB) * HID + dA] = eB * (1.0f / 512.0f);
}

// ---------------- Kernel F: 4-head MLP -> logits ----------------
__global__ void k_mlp(const float* __restrict__ W1s,
                      const float* __restrict__ b1s,
                      const float* __restrict__ W2s,
                      const float* __restrict__ b2s) {
    int n = blockIdx.x;
    int h = threadIdx.x;  // 128
    __shared__ float se[HID];
    __shared__ float red[128];
    se[h] = g_embed[n * HID + h];
    __syncthreads();
    for (int k = 0; k < 4; k++) {
        const float* W1 = W1s + k * HID * HID;
        float acc = b1s[k * HID + h];
#pragma unroll 8
        for (int d = 0; d < HID; d++) acc += se[d] * W1[d * HID + h];
        float r = fmaxf(acc, 0.f) * W2s[k * HID + h];
        red[h] = r;
        __syncthreads();
        for (int off = 64; off > 0; off >>= 1) {
            if (h < off) red[h] += red[h + off];
            __syncthreads();
        }
        if (h == 0) g_logits[k * NN + n] = red[0] + b2s[k];
        __syncthreads();
    }
}

// ---------------- Kernel G: loss + ensemble output ----------------
__global__ void k_final(const int* __restrict__ label,
                        const float* __restrict__ var_raw,
                        float* __restrict__ out) {
    int n = threadIdx.x;  // 512
    __shared__ float cw[4];
    __shared__ float red[NN];
    if (n < 4) {
        float x = var_raw[n];
        cw[n] = (x > 0.f) ? (x + log1pf(expf(-x))) : log1pf(expf(x));
    }
    __syncthreads();
    if (n == 0) {
        float s = cw[0] + cw[1] + cw[2] + cw[3];
        cw[0] /= s; cw[1] /= s; cw[2] /= s; cw[3] /= s;
    }
    __syncthreads();
    float lab = (float)label[0];
    float y = 0.f, lsum = 0.f;
#pragma unroll
    for (int k = 0; k < 4; k++) {
        float L = g_logits[k * NN + n];
        float ls_pos = (L > 0.f) ? -log1pf(expf(-L)) : (L - log1pf(expf(L)));
        float ls_neg = (L < 0.f) ? -log1pf(expf(L)) : (-L - log1pf(expf(-L)));
        lsum += -(lab * ls_pos + (1.f - lab) * ls_neg);
        y += cw[k] * sigf(L);
    }
    red[n] = lsum;
    __syncthreads();
    for (int off = 256; off > 0; off >>= 1) {
        if (n < off) red[n] += red[n + off];
        __syncthreads();
    }
    if (n == 0) out[0] = red[0] * (1.0f / 512.0f);  // sum_k mean_n
    out[1 + n] = y;
}

// ---------------- launcher ----------------
extern "C" void kernel_launch(void* const* d_in, const int* in_sizes, int n_in,
                              void* d_out, int out_size) {
    const int*   tags    = (const int*)d_in[0];
    const float* adj     = (const float*)d_in[1];
    const int*   label   = (const int*)d_in[2];
    const float* W_emb   = (const float*)d_in[3];
    const float* b_emb   = (const float*)d_in[4];
    const float* W_ih    = (const float*)d_in[5];
    const float* W_hh    = (const float*)d_in[6];
    const float* b_ih    = (const float*)d_in[7];
    const float* b_hh    = (const float*)d_in[8];
    const float* W1s     = (const float*)d_in[9];
    const float* b1s     = (const float*)d_in[10];
    const float* W2s     = (const float*)d_in[11];
    const float* b2s     = (const float*)d_in[12];
    const float* var_raw = (const float*)d_in[13];
    float* out = (float*)d_out;

    cudaFuncSetAttribute(k_lstm, cudaFuncAttributeMaxDynamicSharedMemorySize,
                         LSTM_SMEM_BYTES);

    k_embed<<<NN, 64>>>(tags, adj, W_emb, b_emb);
    k_prep_whh<<<(G4 * HID + 255) / 256, 256>>>(W_hh);
    k_ihc<<<NN, G4>>>(W_ih, b_ih, b_hh);
    k_orders<<<NN, 256>>>(adj);
    k_lstm<<<NN / 4, 256, LSTM_SMEM_BYTES>>>();
    k_mlp<<<NN, 128>>>(W1s, b1s, W2s, b2s);
    k_final<<<1, NN>>>(label, var_raw, out);
    (void)in_sizes; (void)n_in; (void)out_size;
}